// round 5
// baseline (speedup 1.0000x reference)
#include <cuda_runtime.h>
#include <cstdint>

#define NNODES 32768
#define EB 8   // edges/nodes per warp batch

__device__ float g_u[NNODES * 64];   // g_a[n] + pos[n]·W1r  (per channel)
__device__ float g_v[NNODES * 64];   // pos[n]·W1r           (per channel)

__device__ __forceinline__ void atomicMaxF(float* addr, float v) {
    if (v >= 0.0f) atomicMax((int*)addr, __float_as_int(v));
    else           atomicMin((unsigned int*)addr, __float_as_uint(v));
}
__device__ __forceinline__ void unpack2(unsigned long long p, float& lo, float& hi) {
    asm("mov.b64 {%0,%1}, %2;" : "=f"(lo), "=f"(hi) : "l"(p));
}
__device__ __forceinline__ void fma2(unsigned long long& acc,
                                     unsigned long long a, unsigned long long b) {
    asm("fma.rn.f32x2 %0, %1, %2, %3;" : "=l"(acc) : "l"(a), "l"(b), "l"(acc));
}

// W2 staged k-pair-major: w2a[q*32+j] = {W2[4q..4q+3][j]}, w2b same for j+32
__device__ __forceinline__ void stage_w2(const float* __restrict__ W2,
                                         float4* w2a, float4* w2b, int tid) {
    for (int idx = tid; idx < 16 * 32; idx += 256) {
        const int q = idx >> 5, j = idx & 31;
        const float* r0 = W2 + (4 * q) * 64;
        w2a[idx] = make_float4(r0[j],      r0[64 + j],      r0[128 + j],      r0[192 + j]);
        w2b[idx] = make_float4(r0[j + 32], r0[64 + j + 32], r0[128 + j + 32], r0[192 + j + 32]);
    }
}

// ---------------------------------------------------------------------------
// Kernel 1: per-node. t = x@W1[0:4]+b1 ; v = pos·W1r ; u = t+v.
// Stores u,v; initializes out with the self-loop value relu(t)@W2 + b2.
// ---------------------------------------------------------------------------
__global__ void __launch_bounds__(256, 2) node_kernel(
    const float* __restrict__ x, const float* __restrict__ pos,
    const float* __restrict__ W1, const float* __restrict__ b1,
    const float* __restrict__ W2, const float* __restrict__ b2,
    float* __restrict__ out)
{
    __shared__ float4 w2a[16 * 32];
    __shared__ float4 w2b[16 * 32];
    __shared__ __align__(16) float tds[8][EB * 64];

    const int tid = threadIdx.x, lane = tid & 31, w = tid >> 5;
    stage_w2(W2, w2a, w2b, tid);
    __syncthreads();
    float* td = tds[w];

    float wxa[4], wxb[4];
#pragma unroll
    for (int i = 0; i < 4; i++) { wxa[i] = W1[i * 64 + lane]; wxb[i] = W1[i * 64 + lane + 32]; }
    const float wra0 = W1[4 * 64 + lane],      wra1 = W1[5 * 64 + lane],      wra2 = W1[6 * 64 + lane];
    const float wrb0 = W1[4 * 64 + lane + 32], wrb1 = W1[5 * 64 + lane + 32], wrb2 = W1[6 * 64 + lane + 32];
    const float b1a = b1[lane], b1b = b1[lane + 32];
    const float b2a = b2[lane], b2b = b2[lane + 32];

    const int gw = blockIdx.x * 8 + w, nW = gridDim.x * 8;
    const int perWarp = (NNODES + nW - 1) / nW;
    const int n0 = gw * perWarp;
    int n1 = n0 + perWarp; if (n1 > NNODES) n1 = NNODES;

    for (int base = n0; base < n1; base += EB) {
        const int nb = min(EB, n1 - base);
        __syncwarp();
#pragma unroll
        for (int i = 0; i < EB; i++) {
            if (i >= nb) break;
            const int n = base + i;
            const float x0 = x[n * 4 + 0], x1 = x[n * 4 + 1];
            const float x2 = x[n * 4 + 2], x3 = x[n * 4 + 3];
            float t0 = fmaf(x3, wxa[3], fmaf(x2, wxa[2], fmaf(x1, wxa[1], fmaf(x0, wxa[0], b1a))));
            float t1 = fmaf(x3, wxb[3], fmaf(x2, wxb[2], fmaf(x1, wxb[1], fmaf(x0, wxb[0], b1b))));
            const float p0 = pos[n * 3 + 0], p1 = pos[n * 3 + 1], p2 = pos[n * 3 + 2];
            const float v0 = fmaf(p2, wra2, fmaf(p1, wra1, p0 * wra0));
            const float v1 = fmaf(p2, wrb2, fmaf(p1, wrb1, p0 * wrb0));
            g_v[(size_t)n * 64 + lane]      = v0;
            g_v[(size_t)n * 64 + 32 + lane] = v1;
            g_u[(size_t)n * 64 + lane]      = t0 + v0;
            g_u[(size_t)n * 64 + 32 + lane] = t1 + v1;
            td[i * 64 + lane]      = fmaxf(t0, 0.0f);
            td[i * 64 + lane + 32] = fmaxf(t1, 0.0f);
        }
        __syncwarp();

        unsigned long long acc[EB][2];
#pragma unroll
        for (int i = 0; i < EB; i++) { acc[i][0] = 0ull; acc[i][1] = 0ull; }
#pragma unroll
        for (int q = 0; q < 16; q++) {
            const ulonglong2 wa = *reinterpret_cast<const ulonglong2*>(&w2a[q * 32 + lane]);
            const ulonglong2 wb = *reinterpret_cast<const ulonglong2*>(&w2b[q * 32 + lane]);
#pragma unroll
            for (int i = 0; i < EB; i++) {
                const ulonglong2 tq = *reinterpret_cast<const ulonglong2*>(&td[i * 64 + q * 4]);
                fma2(acc[i][0], tq.x, wa.x);
                fma2(acc[i][0], tq.y, wa.y);
                fma2(acc[i][1], tq.x, wb.x);
                fma2(acc[i][1], tq.y, wb.y);
            }
        }
#pragma unroll
        for (int i = 0; i < EB; i++) {
            if (i >= nb) break;
            float a, b, c, d;
            unpack2(acc[i][0], a, b);
            unpack2(acc[i][1], c, d);
            const int n = base + i;
            out[(size_t)n * 64 + lane]      = a + b + b2a;
            out[(size_t)n * 64 + 32 + lane] = c + d + b2b;
        }
    }
}

// ---------------------------------------------------------------------------
// Kernel 2: per-edge, software-pipelined, double-buffered t tiles.
//   t_edge = relu(u[src] - v[dst]) ; h = t@W2 + b2 ; segmented max -> atomics.
// ---------------------------------------------------------------------------
__global__ void __launch_bounds__(256, 2) edge_kernel(
    const int* __restrict__ ei, long long E,
    const float* __restrict__ W2, const float* __restrict__ b2,
    float* __restrict__ out)
{
    extern __shared__ char smem[];
    float4* w2a = (float4*)smem;                 //  8 KB
    float4* w2b = (float4*)(smem + 8192);        //  8 KB
    float*  tds = (float*)(smem + 16384);        // 32 KB: [2][8 warps][512]

    const int tid = threadIdx.x, lane = tid & 31, w = tid >> 5;
    stage_w2(W2, w2a, w2b, tid);
    __syncthreads();

    float* tb0 = tds + w * 512;
    float* tb1 = tds + 4096 + w * 512;

    const float b2a = b2[lane], b2b = b2[lane + 32];
    const int* __restrict__ srcA = ei;
    const int* __restrict__ dstA = ei + E;

    const long long gw = blockIdx.x * 8 + w;
    const long long nW = (long long)gridDim.x * 8;
    const long long chunk = (E + nW - 1) / nW;
    const long long e0 = gw * chunk;
    long long e1 = e0 + chunk; if (e1 > E) e1 = E;

    int sN[EB], dN[EB], dC[EB];
    float u0[EB], u1[EB], v0[EB], v1[EB];
    unsigned okC = 0, okN = 0;

    auto loadSD = [&](long long p, int* s, int* d) -> unsigned {
        unsigned ok = 0;
#pragma unroll
        for (int i = 0; i < EB; i++) {
            const long long e = p + i;
            int si = 0, di = 0;
            if (e < e1) {
                si = srcA[e]; di = dstA[e];
                if (si != di) ok |= 1u << i;
            }
            s[i] = si; d[i] = di;
        }
        return ok;
    };
    auto loadUV = [&](const int* s, const int* d) {
#pragma unroll
        for (int i = 0; i < EB; i++) {
            u0[i] = g_u[(size_t)s[i] * 64 + lane];
            u1[i] = g_u[(size_t)s[i] * 64 + 32 + lane];
            v0[i] = g_v[(size_t)d[i] * 64 + lane];
            v1[i] = g_v[(size_t)d[i] * 64 + 32 + lane];
        }
    };
    auto storeT = [&](float* tb) {
#pragma unroll
        for (int i = 0; i < EB; i++) {
            tb[i * 64 + lane]      = fmaxf(u0[i] - v0[i], 0.0f);
            tb[i * 64 + 32 + lane] = fmaxf(u1[i] - v1[i], 0.0f);
        }
    };

    int cur = -1;
    float m0 = -3.4e38f, m1 = -3.4e38f;
    int buf = 0;

    if (e0 < e1) {
        okC = loadSD(e0, sN, dN);
#pragma unroll
        for (int i = 0; i < EB; i++) dC[i] = dN[i];
        loadUV(sN, dN);
        storeT(tb0);
        okN = loadSD(e0 + EB, sN, dN);   // sd one batch ahead
    }

    for (long long base = e0; base < e1; base += EB) {
        __syncwarp();   // prior storeT visible to this gemm

        const long long nxt = base + EB;
        unsigned okF = 0;
        int sF[EB], dF[EB];
        if (nxt < e1) {
            loadUV(sN, dN);                     // data for next batch (issued early)
            okF = loadSD(nxt + EB, sF, dF);     // sd two ahead
        }

        const float* tb = buf ? tb1 : tb0;

        if (okC) {
#pragma unroll
            for (int half = 0; half < 2; half++) {
                unsigned long long acc[4][2];
#pragma unroll
                for (int i = 0; i < 4; i++) { acc[i][0] = 0ull; acc[i][1] = 0ull; }
#pragma unroll
                for (int q = 0; q < 16; q++) {
                    const ulonglong2 wa = *reinterpret_cast<const ulonglong2*>(&w2a[q * 32 + lane]);
                    const ulonglong2 wb = *reinterpret_cast<const ulonglong2*>(&w2b[q * 32 + lane]);
#pragma unroll
                    for (int i = 0; i < 4; i++) {
                        const ulonglong2 tq = *reinterpret_cast<const ulonglong2*>(
                            &tb[(half * 4 + i) * 64 + q * 4]);
                        fma2(acc[i][0], tq.x, wa.x);
                        fma2(acc[i][0], tq.y, wa.y);
                        fma2(acc[i][1], tq.x, wb.x);
                        fma2(acc[i][1], tq.y, wb.y);
                    }
                }
#pragma unroll
                for (int i = 0; i < 4; i++) {
                    const int e = half * 4 + i;
                    if (!((okC >> e) & 1u)) continue;
                    float a, b, c, d2;
                    unpack2(acc[i][0], a, b);
                    unpack2(acc[i][1], c, d2);
                    const float h0 = a + b + b2a;
                    const float h1 = c + d2 + b2b;
                    const int d = dC[e];
                    if (d != cur) {
                        if (cur >= 0) {
                            atomicMaxF(&out[(size_t)cur * 64 + lane],      m0);
                            atomicMaxF(&out[(size_t)cur * 64 + 32 + lane], m1);
                        }
                        cur = d;
                        m0 = -3.4e38f; m1 = -3.4e38f;
                    }
                    m0 = fmaxf(m0, h0);
                    m1 = fmaxf(m1, h1);
                }
            }
        }

        if (nxt < e1) storeT(buf ? tb0 : tb1);   // t for next batch into other buffer

        // rotate pipeline state
        okC = okN;
#pragma unroll
        for (int i = 0; i < EB; i++) dC[i] = dN[i];
        okN = okF;
#pragma unroll
        for (int i = 0; i < EB; i++) { sN[i] = sF[i]; dN[i] = dF[i]; }
        buf ^= 1;
    }
    if (cur >= 0) {
        atomicMaxF(&out[(size_t)cur * 64 + lane],      m0);
        atomicMaxF(&out[(size_t)cur * 64 + 32 + lane], m1);
    }
}

// ---------------------------------------------------------------------------
// Kernel 3: pos + batch (as float) tail of the flattened tuple output.
// ---------------------------------------------------------------------------
__global__ void tail_kernel(const float* __restrict__ pos,
                            const int* __restrict__ batch,
                            float* __restrict__ out, int tail)
{
    int i = blockIdx.x * blockDim.x + threadIdx.x;
    if (i >= tail) return;
    float v;
    if (i < NNODES * 3) v = pos[i];
    else {
        int k = i - NNODES * 3;
        v = (k < NNODES) ? (float)batch[k] : 0.0f;
    }
    out[NNODES * 64 + i] = v;
}

extern "C" void kernel_launch(void* const* d_in, const int* in_sizes, int n_in,
                              void* d_out, int out_size) {
    const float* x     = (const float*)d_in[0];
    const float* pos   = (const float*)d_in[1];
    const int*   batch = (const int*)d_in[2];
    const int*   ei    = (const int*)d_in[3];
    const float* W1    = (const float*)d_in[4];
    const float* b1    = (const float*)d_in[5];
    const float* W2    = (const float*)d_in[6];
    const float* b2    = (const float*)d_in[7];
    float* out = (float*)d_out;

    const long long E = (long long)in_sizes[3] / 2;

    static int smem_set = 0;
    if (!smem_set) {
        cudaFuncSetAttribute(edge_kernel, cudaFuncAttributeMaxDynamicSharedMemorySize, 49152);
        smem_set = 1;
    }

    node_kernel<<<296, 256>>>(x, pos, W1, b1, W2, b2, out);
    edge_kernel<<<296, 256, 49152>>>(ei, E, W2, b2, out);

    int tail = out_size - NNODES * 64;
    if (tail > 0) tail_kernel<<<(tail + 255) / 256, 256>>>(pos, batch, out, tail);
}

// round 6
// speedup vs baseline: 1.8985x; 1.8985x over previous
#include <cuda_runtime.h>
#include <cstdint>

#define NNODES 32768
#define EB 8   // edges/nodes per warp batch

__device__ float g_u[NNODES * 64];   // g_a[n] + pos[n]·W1r
__device__ float g_v[NNODES * 64];   // pos[n]·W1r

__device__ __forceinline__ void atomicMaxF(float* addr, float v) {
    if (v >= 0.0f) atomicMax((int*)addr, __float_as_int(v));
    else           atomicMin((unsigned int*)addr, __float_as_uint(v));
}
__device__ __forceinline__ void unpack2(unsigned long long p, float& lo, float& hi) {
    asm("mov.b64 {%0,%1}, %2;" : "=f"(lo), "=f"(hi) : "l"(p));
}
__device__ __forceinline__ void fma2(unsigned long long& acc,
                                     unsigned long long a, unsigned long long b) {
    asm("fma.rn.f32x2 %0, %1, %2, %3;" : "=l"(acc) : "l"(a), "l"(b), "l"(acc));
}

// W2 staged k-pair-major: w2a[q*32+j] = {W2[4q..4q+3][j]}, w2b same for j+32
__device__ __forceinline__ void stage_w2(const float* __restrict__ W2,
                                         float4* w2a, float4* w2b, int tid, int nthr) {
    for (int idx = tid; idx < 16 * 32; idx += nthr) {
        const int q = idx >> 5, j = idx & 31;
        const float* r0 = W2 + (4 * q) * 64;
        w2a[idx] = make_float4(r0[j],      r0[64 + j],      r0[128 + j],      r0[192 + j]);
        w2b[idx] = make_float4(r0[j + 32], r0[64 + j + 32], r0[128 + j + 32], r0[192 + j + 32]);
    }
}

// ---------------------------------------------------------------------------
// Kernel 1: per-node. t = x@W1[0:4]+b1 ; v = pos·W1r ; u = t+v.
// Stores u,v; initializes out with the self-loop value relu(t)@W2 + b2.
// ---------------------------------------------------------------------------
__global__ void __launch_bounds__(256, 2) node_kernel(
    const float* __restrict__ x, const float* __restrict__ pos,
    const float* __restrict__ W1, const float* __restrict__ b1,
    const float* __restrict__ W2, const float* __restrict__ b2,
    float* __restrict__ out)
{
    __shared__ float4 w2a[16 * 32];
    __shared__ float4 w2b[16 * 32];
    __shared__ __align__(16) float tds[8][EB * 64];

    const int tid = threadIdx.x, lane = tid & 31, w = tid >> 5;
    stage_w2(W2, w2a, w2b, tid, 256);
    __syncthreads();
    float* td = tds[w];

    float wxa[4], wxb[4];
#pragma unroll
    for (int i = 0; i < 4; i++) { wxa[i] = W1[i * 64 + lane]; wxb[i] = W1[i * 64 + lane + 32]; }
    const float wra0 = W1[4 * 64 + lane],      wra1 = W1[5 * 64 + lane],      wra2 = W1[6 * 64 + lane];
    const float wrb0 = W1[4 * 64 + lane + 32], wrb1 = W1[5 * 64 + lane + 32], wrb2 = W1[6 * 64 + lane + 32];
    const float b1a = b1[lane], b1b = b1[lane + 32];
    const float b2a = b2[lane], b2b = b2[lane + 32];

    const int gw = blockIdx.x * 8 + w, nW = gridDim.x * 8;
    const int perWarp = (NNODES + nW - 1) / nW;
    const int n0 = gw * perWarp;
    int n1 = n0 + perWarp; if (n1 > NNODES) n1 = NNODES;

    for (int base = n0; base < n1; base += EB) {
        const int nb = min(EB, n1 - base);
        __syncwarp();
#pragma unroll
        for (int i = 0; i < EB; i++) {
            if (i >= nb) break;
            const int n = base + i;
            const float x0 = x[n * 4 + 0], x1 = x[n * 4 + 1];
            const float x2 = x[n * 4 + 2], x3 = x[n * 4 + 3];
            float t0 = fmaf(x3, wxa[3], fmaf(x2, wxa[2], fmaf(x1, wxa[1], fmaf(x0, wxa[0], b1a))));
            float t1 = fmaf(x3, wxb[3], fmaf(x2, wxb[2], fmaf(x1, wxb[1], fmaf(x0, wxb[0], b1b))));
            const float p0 = pos[n * 3 + 0], p1 = pos[n * 3 + 1], p2 = pos[n * 3 + 2];
            const float v0 = fmaf(p2, wra2, fmaf(p1, wra1, p0 * wra0));
            const float v1 = fmaf(p2, wrb2, fmaf(p1, wrb1, p0 * wrb0));
            g_v[(size_t)n * 64 + lane]      = v0;
            g_v[(size_t)n * 64 + 32 + lane] = v1;
            g_u[(size_t)n * 64 + lane]      = t0 + v0;
            g_u[(size_t)n * 64 + 32 + lane] = t1 + v1;
            td[i * 64 + lane]      = fmaxf(t0, 0.0f);
            td[i * 64 + lane + 32] = fmaxf(t1, 0.0f);
        }
        __syncwarp();

        unsigned long long acc[EB][2];
#pragma unroll
        for (int i = 0; i < EB; i++) { acc[i][0] = 0ull; acc[i][1] = 0ull; }
#pragma unroll
        for (int q = 0; q < 16; q++) {
            const ulonglong2 wa = *reinterpret_cast<const ulonglong2*>(&w2a[q * 32 + lane]);
            const ulonglong2 wb = *reinterpret_cast<const ulonglong2*>(&w2b[q * 32 + lane]);
#pragma unroll
            for (int i = 0; i < EB; i++) {
                const ulonglong2 tq = *reinterpret_cast<const ulonglong2*>(&td[i * 64 + q * 4]);
                fma2(acc[i][0], tq.x, wa.x);
                fma2(acc[i][0], tq.y, wa.y);
                fma2(acc[i][1], tq.x, wb.x);
                fma2(acc[i][1], tq.y, wb.y);
            }
        }
#pragma unroll
        for (int i = 0; i < EB; i++) {
            if (i >= nb) break;
            float a, b, c, d;
            unpack2(acc[i][0], a, b);
            unpack2(acc[i][1], c, d);
            const int n = base + i;
            out[(size_t)n * 64 + lane]      = a + b + b2a;
            out[(size_t)n * 64 + 32 + lane] = c + d + b2b;
        }
    }
}

// ---------------------------------------------------------------------------
// Kernel 2: per-edge. t = relu(u[src] - v[dst]) with segment-cached v[dst]
// (dst-sorted), uniform processing of self-loops/pads (harmless duplicates
// of the node-kernel init under max), whole-batch skip when all s==d.
// ---------------------------------------------------------------------------
__global__ void __launch_bounds__(128, 5) edge_kernel(
    const int* __restrict__ ei, long long E,
    const float* __restrict__ W2, const float* __restrict__ b2,
    float* __restrict__ out)
{
    extern __shared__ char smem[];
    float4* w2a = (float4*)smem;               // 8 KB
    float4* w2b = (float4*)(smem + 8192);      // 8 KB
    float*  tds = (float*)(smem + 16384);      // 8 KB: [4][512]

    const int tid = threadIdx.x, lane = tid & 31, w = tid >> 5;
    stage_w2(W2, w2a, w2b, tid, 128);
    __syncthreads();

    float* tb = tds + w * 512;

    const float b2a = b2[lane], b2b = b2[lane + 32];
    const int* __restrict__ srcA = ei;
    const int* __restrict__ dstA = ei + E;

    const long long gw = blockIdx.x * 4 + w;
    const long long nW = (long long)gridDim.x * 4;
    long long chunk = (E + nW - 1) / nW;
    chunk = (chunk + EB - 1) / EB * EB;        // multiple of EB for aligned int4 loads
    const long long e0 = gw * chunk;
    long long e1 = e0 + chunk; if (e1 > E) e1 = E;

    int cur = -1;                               // flush-segment state
    float m0 = -3.4e38f, m1 = -3.4e38f;
    int dprev = -1;                             // v-cache state
    float vc0 = 0.0f, vc1 = 0.0f;

    for (long long base = e0; base < e1; base += EB) {
        int ss[EB], dd[EB];
        if (base + EB <= E) {
            const int4 s0 = *reinterpret_cast<const int4*>(srcA + base);
            const int4 s1 = *reinterpret_cast<const int4*>(srcA + base + 4);
            const int4 d0 = *reinterpret_cast<const int4*>(dstA + base);
            const int4 d1 = *reinterpret_cast<const int4*>(dstA + base + 4);
            ss[0] = s0.x; ss[1] = s0.y; ss[2] = s0.z; ss[3] = s0.w;
            ss[4] = s1.x; ss[5] = s1.y; ss[6] = s1.z; ss[7] = s1.w;
            dd[0] = d0.x; dd[1] = d0.y; dd[2] = d0.z; dd[3] = d0.w;
            dd[4] = d1.x; dd[5] = d1.y; dd[6] = d1.z; dd[7] = d1.w;
        } else {
#pragma unroll
            for (int i = 0; i < EB; i++) {
                const long long e = base + i;
                ss[i] = (e < E) ? srcA[e] : 0;
                dd[i] = (e < E) ? dstA[e] : 0;
            }
        }

        int nb = (int)min((long long)EB, E - base);
        bool anyreal = false;
#pragma unroll
        for (int i = 0; i < EB; i++)
            if (i < nb && ss[i] != dd[i]) anyreal = true;
        if (!anyreal) continue;                 // pure self-loop/pad batch: already covered by init

        __syncwarp();
#pragma unroll
        for (int i = 0; i < EB; i++) {
            const int s = ss[i], d = (i < nb) ? dd[i] : dd[0];
            if (d != dprev) {                   // uniform across warp
                vc0 = g_v[(size_t)d * 64 + lane];
                vc1 = g_v[(size_t)d * 64 + 32 + lane];
                dprev = d;
            }
            const float uu0 = g_u[(size_t)s * 64 + lane];
            const float uu1 = g_u[(size_t)s * 64 + 32 + lane];
            tb[i * 64 + lane]      = fmaxf(uu0 - vc0, 0.0f);
            tb[i * 64 + 32 + lane] = fmaxf(uu1 - vc1, 0.0f);
        }
        __syncwarp();

        unsigned long long acc[EB][2];
#pragma unroll
        for (int i = 0; i < EB; i++) { acc[i][0] = 0ull; acc[i][1] = 0ull; }
#pragma unroll
        for (int q = 0; q < 16; q++) {
            const ulonglong2 wa = *reinterpret_cast<const ulonglong2*>(&w2a[q * 32 + lane]);
            const ulonglong2 wb = *reinterpret_cast<const ulonglong2*>(&w2b[q * 32 + lane]);
#pragma unroll
            for (int i = 0; i < EB; i++) {
                const ulonglong2 tq = *reinterpret_cast<const ulonglong2*>(&tb[i * 64 + q * 4]);
                fma2(acc[i][0], tq.x, wa.x);
                fma2(acc[i][0], tq.y, wa.y);
                fma2(acc[i][1], tq.x, wb.x);
                fma2(acc[i][1], tq.y, wb.y);
            }
        }

#pragma unroll
        for (int i = 0; i < EB; i++) {
            if (i >= nb) break;
            float a, b, c, d2;
            unpack2(acc[i][0], a, b);
            unpack2(acc[i][1], c, d2);
            const float h0 = a + b + b2a;
            const float h1 = c + d2 + b2b;
            const int d = dd[i];
            if (d != cur) {
                if (cur >= 0) {
                    atomicMaxF(&out[(size_t)cur * 64 + lane],      m0);
                    atomicMaxF(&out[(size_t)cur * 64 + 32 + lane], m1);
                }
                cur = d;
                m0 = -3.4e38f; m1 = -3.4e38f;
            }
            m0 = fmaxf(m0, h0);
            m1 = fmaxf(m1, h1);
        }
    }
    if (cur >= 0) {
        atomicMaxF(&out[(size_t)cur * 64 + lane],      m0);
        atomicMaxF(&out[(size_t)cur * 64 + 32 + lane], m1);
    }
}

// ---------------------------------------------------------------------------
// Kernel 3: pos + batch (as float) tail of the flattened tuple output.
// ---------------------------------------------------------------------------
__global__ void tail_kernel(const float* __restrict__ pos,
                            const int* __restrict__ batch,
                            float* __restrict__ out, int tail)
{
    int i = blockIdx.x * blockDim.x + threadIdx.x;
    if (i >= tail) return;
    float v;
    if (i < NNODES * 3) v = pos[i];
    else {
        int k = i - NNODES * 3;
        v = (k < NNODES) ? (float)batch[k] : 0.0f;
    }
    out[NNODES * 64 + i] = v;
}

extern "C" void kernel_launch(void* const* d_in, const int* in_sizes, int n_in,
                              void* d_out, int out_size) {
    const float* x     = (const float*)d_in[0];
    const float* pos   = (const float*)d_in[1];
    const int*   batch = (const int*)d_in[2];
    const int*   ei    = (const int*)d_in[3];
    const float* W1    = (const float*)d_in[4];
    const float* b1    = (const float*)d_in[5];
    const float* W2    = (const float*)d_in[6];
    const float* b2    = (const float*)d_in[7];
    float* out = (float*)d_out;

    const long long E = (long long)in_sizes[3] / 2;

    cudaFuncSetAttribute(edge_kernel, cudaFuncAttributeMaxDynamicSharedMemorySize, 24576);

    node_kernel<<<296, 256>>>(x, pos, W1, b1, W2, b2, out);
    edge_kernel<<<740, 128, 24576>>>(ei, E, W2, b2, out);

    int tail = out_size - NNODES * 64;
    if (tail > 0) tail_kernel<<<(tail + 255) / 256, 256>>>(pos, batch, out, tail);
}